// round 10
// baseline (speedup 1.0000x reference)
#include <cuda_runtime.h>
#include <cstdint>

#define NTOK   8192
#define HDIM   1024
#define FFDIM  4096
#define NEXP   8
#define NROWS  (NTOK*2)
#define MT_CAP 64                  // max 128-row M-tiles per expert
#define GEMM_THREADS 256
#define ROW_BYTES 128              // 32 floats per smem row (XOR chunk swizzle)
#define TILE_BYTES (128*ROW_BYTES) // 16 KB per operand per stage
#define STAGE_BYTES (2*TILE_BYTES) // 32 KB (A + B)
#define STAGES 3
#define DYN_SMEM (STAGES*STAGE_BYTES)   // 96 KB

// ------------------------- device scratch (static) ----------------------
__device__ int   g_cnt[NEXP];
__device__ int   g_off[NEXP];
__device__ int   g_topk_e[NTOK*2];
__device__ float g_topk_w[NTOK*2];
__device__ int   g_rows_token[NROWS];            // row -> token
__device__ int   g_token_row[NTOK*2];            // token,k -> row
__device__ float g_w1r[(size_t)NEXP*FFDIM*HDIM]; // tf32-rounded+perm w1
__device__ float g_w2r[(size_t)NEXP*HDIM*FFDIM]; // tf32-rounded+perm w2
__device__ float g_xr[(size_t)NTOK*HDIM];        // rounded+perm x (token order)
__device__ float g_y1[(size_t)(NROWS+128)*FFDIM];// rounded+perm intermediate
__device__ float g_out2[(size_t)NROWS*HDIM];     // expert outputs (natural)

// ------------------------- PTX helpers ----------------------------------
__device__ __forceinline__ uint32_t f2tf32(float f){
  uint32_t r; asm("cvt.rna.tf32.f32 %0, %1;" : "=r"(r) : "f"(f)); return r;
}
__device__ __forceinline__ uint32_t smem_u32(const void* p){
  uint32_t a;
  asm("{ .reg .u64 t; cvta.to.shared.u64 t, %1; cvt.u32.u64 %0, t; }" : "=r"(a) : "l"(p));
  return a;
}
#define CP_ASYNC16(dst, src) \
  asm volatile("cp.async.cg.shared.global [%0], [%1], 16;" :: "r"(dst), "l"(src) : "memory")
#define CP_COMMIT() asm volatile("cp.async.commit_group;" ::: "memory")
#define CP_WAIT(N)  asm volatile("cp.async.wait_group %0;" :: "n"(N) : "memory")
#define LDS128(r0, r1, r2, r3, addr) \
  asm volatile("ld.shared.v4.b32 {%0,%1,%2,%3}, [%4];" \
               : "=r"(r0), "=r"(r1), "=r"(r2), "=r"(r3) : "r"(addr))

__device__ __forceinline__ void mma_tf32(float& c0, float& c1, float& c2, float& c3,
                                         uint32_t a0, uint32_t a1, uint32_t a2, uint32_t a3,
                                         uint32_t b0, uint32_t b1){
  asm volatile(
    "mma.sync.aligned.m16n8k8.row.col.f32.tf32.tf32.f32 "
    "{%0,%1,%2,%3}, {%4,%5,%6,%7}, {%8,%9}, {%0,%1,%2,%3};"
    : "+f"(c0), "+f"(c1), "+f"(c2), "+f"(c3)
    : "r"(a0), "r"(a1), "r"(a2), "r"(a3), "r"(b0), "r"(b1));
}
__device__ __forceinline__ float gelu_exact(float v){
  return 0.5f * v * (1.0f + erff(v * 0.70710678118654752f));
}

// ---- K permutation: within each aligned 32-float chunk, pos(k)=(k&3)*8+(k>>2)
// round + permute one 32-float chunk (in: natural floats, out: 8 uint4)
__device__ __forceinline__ void perm32_round(const float* in, uint4* out4){
  #pragma unroll
  for (int q = 0; q < 8; ++q) {
    const int t = q >> 1, u = q & 1;       // out float4 q holds k = t+16u+{0,4,8,12}
    uint4 o;
    o.x = f2tf32(in[t + 16*u + 0]);
    o.y = f2tf32(in[t + 16*u + 4]);
    o.z = f2tf32(in[t + 16*u + 8]);
    o.w = f2tf32(in[t + 16*u + 12]);
    out4[q] = o;
  }
}

// ------------------------- prep: round+permute BOTH weights (+zero cnt) -
__global__ void __launch_bounds__(256) round_w_kernel(const float4* __restrict__ s1,
                                                      uint4* __restrict__ d1,
                                                      const float4* __restrict__ s2,
                                                      uint4* __restrict__ d2, int n32){
  if (blockIdx.x == 0 && threadIdx.x < NEXP) g_cnt[threadIdx.x] = 0;
  int i = blockIdx.x * 256 + threadIdx.x;
  const int stride = gridDim.x * 256;
  for (; i < 2 * n32; i += stride) {
    const float4* src = (i < n32) ? s1 : s2;
    uint4*       dst  = (i < n32) ? d1 : d2;
    const int j = (i < n32) ? i : i - n32;     // 32-float chunk index
    float buf[32];
    float4* b4 = (float4*)buf;
    #pragma unroll
    for (int m = 0; m < 8; ++m) b4[m] = src[j*8 + m];
    uint4 o[8];
    perm32_round(buf, o);
    #pragma unroll
    for (int m = 0; m < 8; ++m) dst[j*8 + m] = o[m];
  }
}

// ------------------------- router (+ write rounded/permuted x) ----------
__global__ void __launch_bounds__(128) moe_router(const float* __restrict__ x,
                                                  const float* __restrict__ rw,
                                                  const float* __restrict__ rb){
  const int lane  = threadIdx.x & 31;
  const int token = blockIdx.x * 4 + (threadIdx.x >> 5);
  const float* xr = x + (size_t)token * HDIM;
  float acc[NEXP];
  #pragma unroll
  for (int e = 0; e < NEXP; ++e) acc[e] = 0.f;
  for (int h = lane; h < HDIM; h += 32) {
    float xv = xr[h];
    #pragma unroll
    for (int e = 0; e < NEXP; ++e) acc[e] += xv * rw[e * HDIM + h];
  }
  #pragma unroll
  for (int e = 0; e < NEXP; ++e) {
    #pragma unroll
    for (int o = 16; o; o >>= 1) acc[e] += __shfl_xor_sync(0xffffffffu, acc[e], o);
  }
  if (lane == 0) {
    float v[NEXP];
    #pragma unroll
    for (int e = 0; e < NEXP; ++e) v[e] = acc[e] + rb[e];
    int e0 = 0; float v0 = v[0];
    #pragma unroll
    for (int e = 1; e < NEXP; ++e) if (v[e] > v0) { v0 = v[e]; e0 = e; }
    int e1 = (e0 == 0) ? 1 : 0; float v1 = v[e1];
    #pragma unroll
    for (int e = 0; e < NEXP; ++e) if (e != e0 && v[e] > v1) { v1 = v[e]; e1 = e; }
    float t  = expf(v1 - v0);
    float w0 = 1.f / (1.f + t);
    g_topk_e[2*token]   = e0;  g_topk_e[2*token+1] = e1;
    g_topk_w[2*token]   = w0;  g_topk_w[2*token+1] = t * w0;
    atomicAdd(&g_cnt[e0], 1);  atomicAdd(&g_cnt[e1], 1);
  }
  // rounded + permuted copy: lane handles 32-float chunk `lane` (HDIM/32 = 32)
  {
    const float4* srcv = (const float4*)xr;
    uint4* dstv = (uint4*)(g_xr + (size_t)token * HDIM);
    float buf[32];
    float4* b4 = (float4*)buf;
    #pragma unroll
    for (int m = 0; m < 8; ++m) b4[m] = srcv[lane*8 + m];
    uint4 o[8];
    perm32_round(buf, o);
    #pragma unroll
    for (int m = 0; m < 8; ++m) dstv[lane*8 + m] = o[m];
  }
}

// ------------------------- offsets + scatter (single block) -------------
__global__ void __launch_bounds__(1024) routing_finalize(){
  __shared__ int s_cur[NEXP];
  if (threadIdx.x == 0) {
    int o = 0;
    #pragma unroll
    for (int e = 0; e < NEXP; ++e) { g_off[e] = o; s_cur[e] = o; o += g_cnt[e]; }
  }
  __syncthreads();
  for (int t = threadIdx.x; t < NTOK; t += 1024) {
    #pragma unroll
    for (int k = 0; k < 2; ++k) {
      int e = g_topk_e[2*t + k];
      int pos = atomicAdd(&s_cur[e], 1);
      g_rows_token[pos]  = t;
      g_token_row[2*t+k] = pos;
    }
  }
}

// ------------------------- grouped tf32 mma.sync GEMM -------------------
// K permuted per 32-chunk: pos(k)=(k&3)*8+(k>>2), so one thread's fragment
// data for ks in {0,1} (resp {2,3}) is 16 contiguous bytes -> LDS.128.
// Smem: 128B rows, XOR chunk swizzle chunk_phys = chunk ^ (row&7).
template<bool FIRST>
__global__ void __launch_bounds__(GEMM_THREADS, 2)
moe_gemm(const float* __restrict__ A, const float* __restrict__ W,
         const float* __restrict__ bias, float* __restrict__ out,
         int Kdim, int Ndim)
{
  const int tid  = threadIdx.x;
  const int lane = tid & 31;
  const int wid  = tid >> 5;
  const int e    = blockIdx.x >> 6;
  const int mt   = blockIdx.x & (MT_CAP - 1);
  const int cnt  = g_cnt[e];
  if (mt * 128 >= cnt) return;
  const int m0    = g_off[e] + mt * 128;
  const int valid = min(128, cnt - mt * 128);
  const int n0    = blockIdx.y * 128;

  __shared__ const float* s_aptr[128];
  extern __shared__ __align__(16) char dsm[];
  const uint32_t dyn0 = smem_u32(dsm);

  if (FIRST && tid < 128) {
    int r   = tid;
    int tok = g_rows_token[m0 + min(r, valid - 1)];
    s_aptr[r] = A + (size_t)tok * Kdim;
  }
  __syncthreads();

  const float* abase = A + (size_t)m0 * Kdim;   // contiguous path (GEMM2)
  const float* wbase = W + ((size_t)e * Ndim + n0) * Kdim;
  const int nch = Kdim >> 5;

  const int cr  = tid >> 3;                    // base row 0..31
  const int ckq = tid & 7;                     // logical 16B chunk in 32-float k-chunk
  const uint32_t dquad = (uint32_t)((ckq ^ (cr & 7)) * 16);   // XOR swizzled byte off

  auto issue = [&](int c, uint32_t stoff){
    const uint32_t aS = dyn0 + stoff;
    const uint32_t bS = aS + TILE_BYTES;
    const int k0 = c << 5;
    #pragma unroll
    for (int j = 0; j < 4; ++j) {
      const int r = cr + 32 * j;               // (r&7)==(cr&7): dquad valid
      const float* srcA = FIRST ? (s_aptr[r] + k0 + ckq * 4)
                                : (abase + (size_t)r * Kdim + k0 + ckq * 4);
      CP_ASYNC16(aS + (uint32_t)(r * ROW_BYTES) + dquad, srcA);
      CP_ASYNC16(bS + (uint32_t)(r * ROW_BYTES) + dquad,
                 wbase + (size_t)r * Kdim + k0 + ckq * 4);
    }
  };

  issue(0, 0); CP_COMMIT();
  issue(1, STAGE_BYTES); CP_COMMIT();

  const int wRow = wid >> 1;                   // 0..3 -> M*32
  const int wCol = wid & 1;                    // 0..1 -> N*64
  const int g    = lane >> 2;
  const int tig  = lane & 3;

  // byte offset within a row for kspair kp: chunk (2*tig+kp) ^ (g&7)
  uint32_t off_kp[2];
  #pragma unroll
  for (int kp = 0; kp < 2; ++kp)
    off_kp[kp] = (uint32_t)((((2*tig + kp) ^ (g & 7)) * 16));

  // loop-invariant warp/lane smem row bases
  const uint32_t awb = dyn0 + (uint32_t)((wRow*32 + g) * ROW_BYTES);
  const uint32_t bwb = dyn0 + TILE_BYTES + (uint32_t)((wCol*64 + g) * ROW_BYTES);

  float acc[2][8][4];
  #pragma unroll
  for (int mf = 0; mf < 2; ++mf)
    #pragma unroll
    for (int nf = 0; nf < 8; ++nf)
      #pragma unroll
      for (int q = 0; q < 4; ++q) acc[mf][nf][q] = 0.f;

  uint32_t stoff_c = 0, stoff_n = 2u * STAGE_BYTES;
  for (int c = 0; c < nch; ++c) {
    CP_WAIT(STAGES - 2);
    __syncthreads();
    if (c + STAGES - 1 < nch) issue(c + STAGES - 1, stoff_n);
    CP_COMMIT();

    const uint32_t aw = awb + stoff_c;
    const uint32_t bw = bwb + stoff_c;

    #pragma unroll
    for (int kp = 0; kp < 2; ++kp) {           // kspair: ks = 2kp, 2kp+1
      const uint32_t ak = aw + off_kp[kp];
      const uint32_t bk = bw + off_kp[kp];
      uint32_t aF[2][2][4];                    // [ks_in][mf][frag]
      #pragma unroll
      for (int mf = 0; mf < 2; ++mf) {
        LDS128(aF[0][mf][0], aF[0][mf][2], aF[1][mf][0], aF[1][mf][2],
               ak + mf*2048);                  // row wRow*32+mf*16+g
        LDS128(aF[0][mf][1], aF[0][mf][3], aF[1][mf][1], aF[1][mf][3],
               ak + mf*2048 + 1024);           // row +8
      }
      #pragma unroll
      for (int nf = 0; nf < 8; ++nf) {
        uint32_t b00, b01, b10, b11;
        LDS128(b00, b01, b10, b11, bk + nf*1024);   // col wCol*64+nf*8+g
        // per-accumulator ks order: 2kp then 2kp+1 (bit-identical to before)
        mma_tf32(acc[0][nf][0], acc[0][nf][1], acc[0][nf][2], acc[0][nf][3],
                 aF[0][0][0], aF[0][0][1], aF[0][0][2], aF[0][0][3], b00, b01);
        mma_tf32(acc[0][nf][0], acc[0][nf][1], acc[0][nf][2], acc[0][nf][3],
                 aF[1][0][0], aF[1][0][1], aF[1][0][2], aF[1][0][3], b10, b11);
        mma_tf32(acc[1][nf][0], acc[1][nf][1], acc[1][nf][2], acc[1][nf][3],
                 aF[0][1][0], aF[0][1][1], aF[0][1][2], aF[0][1][3], b00, b01);
        mma_tf32(acc[1][nf][0], acc[1][nf][1], acc[1][nf][2], acc[1][nf][3],
                 aF[1][1][0], aF[1][1][1], aF[1][1][2], aF[1][1][3], b10, b11);
      }
    }
    stoff_c += STAGE_BYTES; if (stoff_c == STAGES*STAGE_BYTES) stoff_c = 0;
    stoff_n += STAGE_BYTES; if (stoff_n == STAGES*STAGE_BYTES) stoff_n = 0;
  }

  // ---------------- epilogue ---------------------------------------------
  const float* bptr = bias + (size_t)e * Ndim + n0;
  // FIRST scatter: within each 32-col chunk, pos(c)=(c&3)*8+(c>>2)
  const int pbase = (((2*tig) & 3) << 3) + (tig >> 1);
  #pragma unroll
  for (int mf = 0; mf < 2; ++mf) {
    #pragma unroll
    for (int half = 0; half < 2; ++half) {
      const int rl = wRow * 32 + mf * 16 + g + half * 8;
      if (rl < valid) {
        float* orow = out + (size_t)(m0 + rl) * Ndim + n0;
        #pragma unroll
        for (int nf = 0; nf < 8; ++nf) {
          const int nbase = wCol * 64 + nf * 8;
          float v0 = acc[mf][nf][half*2 + 0] + bptr[nbase + 2*tig];
          float v1 = acc[mf][nf][half*2 + 1] + bptr[nbase + 2*tig + 1];
          if (FIRST) {
            v0 = gelu_exact(v0); v1 = gelu_exact(v1);
            const int ocol = wCol*64 + ((nf >> 2) << 5) + ((nf & 3) << 1) + pbase;
            orow[ocol]     = __uint_as_float(f2tf32(v0));
            orow[ocol + 8] = __uint_as_float(f2tf32(v1));
          } else {
            float2 v; v.x = v0; v.y = v1;
            *(float2*)(orow + nbase + 2*tig) = v;
          }
        }
      }
    }
  }
}

// ------------------------- combine + residual + LN ----------------------
__global__ void __launch_bounds__(256) moe_final_ln(const float* __restrict__ x,
                                                    const float* __restrict__ lnw,
                                                    const float* __restrict__ lnb,
                                                    float* __restrict__ out){
  __shared__ float ps[8], ps2[8], s_mu, s_rs;
  const int t  = blockIdx.x;
  const int r0 = g_token_row[2*t], r1 = g_token_row[2*t+1];
  const float w0 = g_topk_w[2*t],  w1 = g_topk_w[2*t+1];
  const float* xr = x      + (size_t)t  * HDIM;
  const float* a0 = g_out2 + (size_t)r0 * HDIM;
  const float* a1 = g_out2 + (size_t)r1 * HDIM;
  float v[4]; float s = 0.f, s2 = 0.f;
  #pragma unroll
  for (int j = 0; j < 4; ++j) {
    int h = threadIdx.x + 256 * j;
    float val = xr[h] + w0 * a0[h] + w1 * a1[h];
    v[j] = val; s += val; s2 += val * val;
  }
  #pragma unroll
  for (int o = 16; o; o >>= 1) {
    s  += __shfl_xor_sync(0xffffffffu, s,  o);
    s2 += __shfl_xor_sync(0xffffffffu, s2, o);
  }
  const int wd = threadIdx.x >> 5, lane = threadIdx.x & 31;
  if (lane == 0) { ps[wd] = s; ps2[wd] = s2; }
  __syncthreads();
  if (threadIdx.x == 0) {
    float S = 0.f, S2 = 0.f;
    #pragma unroll
    for (int i = 0; i < 8; ++i) { S += ps[i]; S2 += ps2[i]; }
    float mu  = S * (1.f / HDIM);
    float var = S2 * (1.f / HDIM) - mu * mu;
    s_mu = mu; s_rs = rsqrtf(var + 1e-12f);
  }
  __syncthreads();
  const float mu = s_mu, rs = s_rs;
  #pragma unroll
  for (int j = 0; j < 4; ++j) {
    int h = threadIdx.x + 256 * j;
    out[(size_t)t * HDIM + h] = (v[j] - mu) * rs * lnw[h] + lnb[h];
  }
}

// ------------------------- launch ---------------------------------------
extern "C" void kernel_launch(void* const* d_in, const int* in_sizes, int n_in,
                              void* d_out, int out_size){
  (void)in_sizes; (void)n_in; (void)out_size;
  const float* x   = (const float*)d_in[0];
  const float* rw  = (const float*)d_in[1];
  const float* rb  = (const float*)d_in[2];
  const float* w1  = (const float*)d_in[3];
  const float* b1  = (const float*)d_in[4];
  const float* w2  = (const float*)d_in[5];
  const float* b2  = (const float*)d_in[6];
  const float* lnw = (const float*)d_in[7];
  const float* lnb = (const float*)d_in[8];
  float* out = (float*)d_out;

  float* w1r; cudaGetSymbolAddress((void**)&w1r, g_w1r);
  float* w2r; cudaGetSymbolAddress((void**)&w2r, g_w2r);
  float* xrp; cudaGetSymbolAddress((void**)&xrp, g_xr);
  float* y1p; cudaGetSymbolAddress((void**)&y1p, g_y1);
  float* o2p; cudaGetSymbolAddress((void**)&o2p, g_out2);

  cudaFuncSetAttribute(moe_gemm<true >, cudaFuncAttributeMaxDynamicSharedMemorySize, DYN_SMEM);
  cudaFuncSetAttribute(moe_gemm<false>, cudaFuncAttributeMaxDynamicSharedMemorySize, DYN_SMEM);

  const int N32 = (int)((size_t)NEXP * FFDIM * HDIM / 32);  // 32-float chunks per weight

  // launch index 3 (0-based) = GEMM1 -> profiled by the fixed ncu bounds
  round_w_kernel<<<8192, 256>>>((const float4*)w1, (uint4*)w1r,
                                (const float4*)w2, (uint4*)w2r, N32);     // 0 (+zero cnt)
  moe_router<<<NTOK/4, 128>>>(x, rw, rb);                                  // 1
  routing_finalize<<<1, 1024>>>();                                        // 2
  moe_gemm<true ><<<dim3(NEXP*MT_CAP, FFDIM/128), GEMM_THREADS, DYN_SMEM>>>(
      xrp, w1r, b1, y1p, HDIM, FFDIM);                                    // 3: GEMM1
  moe_gemm<false><<<dim3(NEXP*MT_CAP, HDIM/128), GEMM_THREADS, DYN_SMEM>>>(
      y1p, w2r, b2, o2p, FFDIM, HDIM);                                    // 4: GEMM2
  moe_final_ln<<<NTOK, 256>>>(x, lnw, lnb, out);                          // 5
}

// round 11
// speedup vs baseline: 1.3630x; 1.3630x over previous
#include <cuda_runtime.h>
#include <cuda_fp16.h>
#include <cstdint>

#define NTOK   8192
#define HDIM   1024
#define FFDIM  4096
#define NEXP   8
#define NROWS  (NTOK*2)
#define MT_CAP 64                  // max 128-row M-tiles per expert
#define GEMM_THREADS 256
#define ROW_BYTES 128              // 32 floats / 64 fp16-bytes per smem row
#define TILE_BYTES (128*ROW_BYTES) // 16 KB per operand per stage
#define STAGE_BYTES (2*TILE_BYTES) // 32 KB (A + B)
#define STAGES 3
#define DYN_SMEM (STAGES*STAGE_BYTES)   // 96 KB

// ------------------------- device scratch (static) ----------------------
__device__ int    g_cnt[NEXP];
__device__ int    g_off[NEXP];
__device__ int    g_topk_e[NTOK*2];
__device__ float  g_topk_w[NTOK*2];
__device__ int    g_rows_token[NROWS];            // row -> token
__device__ int    g_token_row[NTOK*2];            // token,k -> row
__device__ float  g_w1r[(size_t)NEXP*FFDIM*HDIM]; // tf32-rounded+perm8 w1
__device__ __half g_w2h[(size_t)NEXP*HDIM*FFDIM]; // fp16+perm16 w2
__device__ float  g_xr[(size_t)NTOK*HDIM];        // tf32+perm8 x (token order)
__device__ __half g_y1h[(size_t)(NROWS+128)*FFDIM];// fp16+perm16 intermediate
__device__ float  g_out2[(size_t)NROWS*HDIM];     // expert outputs (natural)

// ------------------------- PTX helpers ----------------------------------
__device__ __forceinline__ uint32_t f2tf32(float f){
  uint32_t r; asm("cvt.rna.tf32.f32 %0, %1;" : "=r"(r) : "f"(f)); return r;
}
__device__ __forceinline__ uint32_t smem_u32(const void* p){
  uint32_t a;
  asm("{ .reg .u64 t; cvta.to.shared.u64 t, %1; cvt.u32.u64 %0, t; }" : "=r"(a) : "l"(p));
  return a;
}
#define CP_ASYNC16(dst, src) \
  asm volatile("cp.async.cg.shared.global [%0], [%1], 16;" :: "r"(dst), "l"(src) : "memory")
#define CP_COMMIT() asm volatile("cp.async.commit_group;" ::: "memory")
#define CP_WAIT(N)  asm volatile("cp.async.wait_group %0;" :: "n"(N) : "memory")
#define LDS64(lo, hi, addr) \
  asm volatile("ld.shared.v2.b32 {%0,%1}, [%2];" : "=r"(lo), "=r"(hi) : "r"(addr))

__device__ __forceinline__ void mma_tf32(float& c0, float& c1, float& c2, float& c3,
                                         uint32_t a0, uint32_t a1, uint32_t a2, uint32_t a3,
                                         uint32_t b0, uint32_t b1){
  asm volatile(
    "mma.sync.aligned.m16n8k8.row.col.f32.tf32.tf32.f32 "
    "{%0,%1,%2,%3}, {%4,%5,%6,%7}, {%8,%9}, {%0,%1,%2,%3};"
    : "+f"(c0), "+f"(c1), "+f"(c2), "+f"(c3)
    : "r"(a0), "r"(a1), "r"(a2), "r"(a3), "r"(b0), "r"(b1));
}
__device__ __forceinline__ void mma_f16(float& c0, float& c1, float& c2, float& c3,
                                        uint32_t a0, uint32_t a1, uint32_t a2, uint32_t a3,
                                        uint32_t b0, uint32_t b1){
  asm volatile(
    "mma.sync.aligned.m16n8k16.row.col.f32.f16.f16.f32 "
    "{%0,%1,%2,%3}, {%4,%5,%6,%7}, {%8,%9}, {%0,%1,%2,%3};"
    : "+f"(c0), "+f"(c1), "+f"(c2), "+f"(c3)
    : "r"(a0), "r"(a1), "r"(a2), "r"(a3), "r"(b0), "r"(b1));
}
__device__ __forceinline__ float gelu_exact(float v){
  return 0.5f * v * (1.0f + erff(v * 0.70710678118654752f));
}
__device__ __forceinline__ uint32_t h2pack(float a, float b){
  __half2 h = __floats2half2_rn(a, b);
  return *(uint32_t*)&h;
}

// tf32 round + pairwise k-permute one aligned 8-float group:
// out = {f0,f4,f1,f5,f2,f6,f3,f7}
__device__ __forceinline__ void perm8_round(const float4 lo, const float4 hi, uint4& o0, uint4& o1){
  o0.x = f2tf32(lo.x); o0.y = f2tf32(hi.x); o0.z = f2tf32(lo.y); o0.w = f2tf32(hi.y);
  o1.x = f2tf32(lo.z); o1.y = f2tf32(hi.z); o1.z = f2tf32(lo.w); o1.w = f2tf32(hi.w);
}

// ------------------------- prep: w1 tf32+perm8 (+zero counts) -----------
__global__ void __launch_bounds__(256) round_w1_kernel(const float4* __restrict__ src,
                                                       uint4* __restrict__ dst, int n8){
  if (blockIdx.x == 0 && threadIdx.x < NEXP) g_cnt[threadIdx.x] = 0;
  int i = blockIdx.x * 256 + threadIdx.x;
  const int stride = gridDim.x * 256;
  for (; i < n8; i += stride) {
    float4 lo = src[2*i], hi = src[2*i+1];
    uint4 o0, o1;
    perm8_round(lo, hi, o0, o1);
    dst[2*i] = o0; dst[2*i+1] = o1;
  }
}

// ------------------------- prep: w2 fp16+perm16 -------------------------
// fp16 K-permutation within aligned 16-group: pos(8h+2t+b) = 4t+2h+b
__global__ void __launch_bounds__(256) round_w2_kernel(const float4* __restrict__ src,
                                                       uint4* __restrict__ dst, int n16){
  int i = blockIdx.x * 256 + threadIdx.x;
  const int stride = gridDim.x * 256;
  for (; i < n16; i += stride) {
    float4 a = src[4*i], b = src[4*i+1], c = src[4*i+2], d = src[4*i+3];
    // f[0..15] = a.xyzw b.xyzw c.xyzw d.xyzw
    uint4 o0, o1;
    o0.x = h2pack(a.x, a.y);   // pos 0,1  <- f0,f1
    o0.y = h2pack(c.x, c.y);   // pos 2,3  <- f8,f9
    o0.z = h2pack(a.z, a.w);   // pos 4,5  <- f2,f3
    o0.w = h2pack(c.z, c.w);   // pos 6,7  <- f10,f11
    o1.x = h2pack(b.x, b.y);   // pos 8,9  <- f4,f5
    o1.y = h2pack(d.x, d.y);   // pos 10,11<- f12,f13
    o1.z = h2pack(b.z, b.w);   // pos 12,13<- f6,f7
    o1.w = h2pack(d.z, d.w);   // pos 14,15<- f14,f15
    dst[2*i] = o0; dst[2*i+1] = o1;
  }
}

// ------------------------- router (+ write tf32/perm8 x) ----------------
__global__ void __launch_bounds__(128) moe_router(const float* __restrict__ x,
                                                  const float* __restrict__ rw,
                                                  const float* __restrict__ rb){
  const int lane  = threadIdx.x & 31;
  const int token = blockIdx.x * 4 + (threadIdx.x >> 5);
  const float* xr = x + (size_t)token * HDIM;
  float acc[NEXP];
  #pragma unroll
  for (int e = 0; e < NEXP; ++e) acc[e] = 0.f;
  for (int h = lane; h < HDIM; h += 32) {
    float xv = xr[h];
    #pragma unroll
    for (int e = 0; e < NEXP; ++e) acc[e] += xv * rw[e * HDIM + h];
  }
  #pragma unroll
  for (int e = 0; e < NEXP; ++e) {
    #pragma unroll
    for (int o = 16; o; o >>= 1) acc[e] += __shfl_xor_sync(0xffffffffu, acc[e], o);
  }
  if (lane == 0) {
    float v[NEXP];
    #pragma unroll
    for (int e = 0; e < NEXP; ++e) v[e] = acc[e] + rb[e];
    int e0 = 0; float v0 = v[0];
    #pragma unroll
    for (int e = 1; e < NEXP; ++e) if (v[e] > v0) { v0 = v[e]; e0 = e; }
    int e1 = (e0 == 0) ? 1 : 0; float v1 = v[e1];
    #pragma unroll
    for (int e = 0; e < NEXP; ++e) if (e != e0 && v[e] > v1) { v1 = v[e]; e1 = e; }
    float t  = expf(v1 - v0);
    float w0 = 1.f / (1.f + t);
    g_topk_e[2*token]   = e0;  g_topk_e[2*token+1] = e1;
    g_topk_w[2*token]   = w0;  g_topk_w[2*token+1] = t * w0;
    atomicAdd(&g_cnt[e0], 1);  atomicAdd(&g_cnt[e1], 1);
  }
  // tf32-rounded + perm8 copy of this token's row
  const float4* srcv = (const float4*)xr;
  uint4* dstv = (uint4*)(g_xr + (size_t)token * HDIM);
  #pragma unroll
  for (int j = 0; j < 4; ++j) {
    int g8 = lane + 32 * j;
    float4 lo = srcv[2*g8], hi = srcv[2*g8+1];
    uint4 o0, o1;
    perm8_round(lo, hi, o0, o1);
    dstv[2*g8] = o0; dstv[2*g8+1] = o1;
  }
}

// ------------------------- offsets + scatter (single block) -------------
__global__ void __launch_bounds__(1024) routing_finalize(){
  __shared__ int s_cur[NEXP];
  if (threadIdx.x == 0) {
    int o = 0;
    #pragma unroll
    for (int e = 0; e < NEXP; ++e) { g_off[e] = o; s_cur[e] = o; o += g_cnt[e]; }
  }
  __syncthreads();
  for (int t = threadIdx.x; t < NTOK; t += 1024) {
    #pragma unroll
    for (int k = 0; k < 2; ++k) {
      int e = g_topk_e[2*t + k];
      int pos = atomicAdd(&s_cur[e], 1);
      g_rows_token[pos]  = t;
      g_token_row[2*t+k] = pos;
    }
  }
}

// ------------------------- GEMM1: tf32 (R8-proven core) -----------------
// y1h = fp16_perm16( gelu(x_gathered @ w1r^T + b1) )
__global__ void __launch_bounds__(GEMM_THREADS, 2)
moe_gemm1(const float* __restrict__ A, const float* __restrict__ W,
          const float* __restrict__ bias, __half* __restrict__ out,
          int Kdim, int Ndim)
{
  const int tid  = threadIdx.x;
  const int lane = tid & 31;
  const int wid  = tid >> 5;
  const int e    = blockIdx.x >> 6;
  const int mt   = blockIdx.x & (MT_CAP - 1);
  const int cnt  = g_cnt[e];
  if (mt * 128 >= cnt) return;
  const int m0    = g_off[e] + mt * 128;
  const int valid = min(128, cnt - mt * 128);
  const int n0    = blockIdx.y * 128;

  __shared__ const float* s_aptr[128];
  extern __shared__ __align__(16) char dsm[];
  const uint32_t dyn0 = smem_u32(dsm);

  if (tid < 128) {
    int r   = tid;
    int tok = g_rows_token[m0 + min(r, valid - 1)];
    s_aptr[r] = A + (size_t)tok * Kdim;
  }
  __syncthreads();

  const float* wbase = W + ((size_t)e * Ndim + n0) * Kdim;
  const int nch = Kdim >> 5;

  const int cr  = tid >> 3;                    // base row 0..31
  const int ckq = tid & 7;                     // 16B quad in 32-float chunk
  const uint32_t dquad = (uint32_t)(8 * ((2*ckq + 4*(cr & 3)) & 15));

  auto issue = [&](int c, uint32_t stoff){
    const uint32_t aS = dyn0 + stoff;
    const uint32_t bS = aS + TILE_BYTES;
    const int k0 = c << 5;
    #pragma unroll
    for (int j = 0; j < 4; ++j) {
      const int r = cr + 32 * j;
      CP_ASYNC16(aS + (uint32_t)(r * ROW_BYTES) + dquad, s_aptr[r] + k0 + ckq * 4);
      CP_ASYNC16(bS + (uint32_t)(r * ROW_BYTES) + dquad,
                 wbase + (size_t)r * Kdim + k0 + ckq * 4);
    }
  };

  issue(0, 0); CP_COMMIT();
  issue(1, STAGE_BYTES); CP_COMMIT();

  const int wRow = wid >> 1;                   // 0..3 -> M*32
  const int wCol = wid & 1;                    // 0..1 -> N*64
  const int g    = lane >> 2;
  const int tig  = lane & 3;
  const int t0   = tig + 4 * (g & 3);

  uint32_t slot8[4];
  #pragma unroll
  for (int ks = 0; ks < 4; ++ks) slot8[ks] = (uint32_t)(((4*ks + t0) & 15) * 8);

  const uint32_t awb = dyn0 + (uint32_t)((wRow*32 + g) * ROW_BYTES);
  const uint32_t bwb = dyn0 + TILE_BYTES + (uint32_t)((wCol*64 + g) * ROW_BYTES);

  float acc[2][8][4];
  #pragma unroll
  for (int mf = 0; mf < 2; ++mf)
    #pragma unroll
    for (int nf = 0; nf < 8; ++nf)
      #pragma unroll
      for (int q = 0; q < 4; ++q) acc[mf][nf][q] = 0.f;

  uint32_t stoff_c = 0, stoff_n = 2u * STAGE_BYTES;
  for (int c = 0; c < nch; ++c) {
    CP_WAIT(STAGES - 2);
    __syncthreads();
    if (c + STAGES - 1 < nch) issue(c + STAGES - 1, stoff_n);
    CP_COMMIT();

    const uint32_t aw = awb + stoff_c;
    const uint32_t bw = bwb + stoff_c;

    #pragma unroll
    for (int ks = 0; ks < 4; ++ks) {
      const uint32_t ak = aw + slot8[ks];
      const uint32_t bk = bw + slot8[ks];
      uint32_t aF[2][4];
      LDS64(aF[0][0], aF[0][2], ak);
      LDS64(aF[0][1], aF[0][3], ak + 8*ROW_BYTES);
      LDS64(aF[1][0], aF[1][2], ak + 16*ROW_BYTES);
      LDS64(aF[1][1], aF[1][3], ak + 24*ROW_BYTES);
      uint32_t bF[8][2];
      #pragma unroll
      for (int nf = 0; nf < 8; ++nf)
        LDS64(bF[nf][0], bF[nf][1], bk + nf*(8*ROW_BYTES));
      #pragma unroll
      for (int mf = 0; mf < 2; ++mf)
        #pragma unroll
        for (int nf = 0; nf < 8; ++nf)
          mma_tf32(acc[mf][nf][0], acc[mf][nf][1], acc[mf][nf][2], acc[mf][nf][3],
                   aF[mf][0], aF[mf][1], aF[mf][2], aF[mf][3],
                   bF[nf][0], bF[nf][1]);
    }
    stoff_c += STAGE_BYTES; if (stoff_c == STAGES*STAGE_BYTES) stoff_c = 0;
    stoff_n += STAGE_BYTES; if (stoff_n == STAGES*STAGE_BYTES) stoff_n = 0;
  }

  // epilogue: bias + gelu, fp16 round, perm16 scatter
  // logical cols c0 = wCol*64+nf*8+2tig, c0+1  -> half2 at
  //   (wCol*4 + (nf>>1))*16 + 4*tig + 2*(nf&1)
  const float* bptr = bias + (size_t)e * Ndim + n0;
  #pragma unroll
  for (int mf = 0; mf < 2; ++mf) {
    #pragma unroll
    for (int half = 0; half < 2; ++half) {
      const int rl = wRow * 32 + mf * 16 + g + half * 8;
      if (rl < valid) {
        __half* orow = out + (size_t)(m0 + rl) * Ndim + n0;
        #pragma unroll
        for (int nf = 0; nf < 8; ++nf) {
          const int nbase = wCol * 64 + nf * 8;
          float v0 = acc[mf][nf][half*2 + 0] + bptr[nbase + 2*tig];
          float v1 = acc[mf][nf][half*2 + 1] + bptr[nbase + 2*tig + 1];
          v0 = gelu_exact(v0); v1 = gelu_exact(v1);
          const int ocol = (wCol*4 + (nf >> 1))*16 + 4*tig + 2*(nf & 1);
          __half2 hv = __floats2half2_rn(v0, v1);
          *(__half2*)(orow + ocol) = hv;
        }
      }
    }
  }
}

// ------------------------- GEMM2: fp16 m16n8k16 -------------------------
// out2 = y1h @ w2h^T + b2   [rows x H], K = FF (halves, perm16)
// smem rows: 64B data in 128B rows; 8B-slot s_log = 4u+tig placed at
// (s_log + 4*(row&3)) & 15 (== 16B quad (q_log + 2*(row&3)) & 7).
__global__ void __launch_bounds__(GEMM_THREADS, 2)
moe_gemm2(const __half* __restrict__ A, const __half* __restrict__ W,
          const float* __restrict__ bias, float* __restrict__ out,
          int Kdim, int Ndim)
{
  const int tid  = threadIdx.x;
  const int lane = tid & 31;
  const int wid  = tid >> 5;
  const int e    = blockIdx.x >> 6;
  const int mt   = blockIdx.x & (MT_CAP - 1);
  const int cnt  = g_cnt[e];
  if (mt * 128 >= cnt) return;
  const int m0    = g_off[e] + mt * 128;
  const int valid = min(128, cnt - mt * 128);
  const int n0    = blockIdx.y * 128;

  extern __shared__ __align__(16) char dsm[];
  const uint32_t dyn0 = smem_u32(dsm);

  const __half* abase = A + (size_t)m0 * Kdim;
  const __half* wbase = W + ((size_t)e * Ndim + n0) * Kdim;
  const int nch = Kdim >> 5;                   // 32 halves per chunk

  const int cr = tid >> 2;                     // base row 0..63
  const int cq = tid & 3;                      // logical 16B quad (0..3)
  const uint32_t dquad = (uint32_t)(((cq + 2*(cr & 3)) & 7) * 16);

  auto issue = [&](int c, uint32_t stoff){
    const uint32_t aS = dyn0 + stoff;
    const uint32_t bS = aS + TILE_BYTES;
    const int k0 = c << 5;                     // halves
    #pragma unroll
    for (int j = 0; j < 2; ++j) {
      const int r = cr + 64 * j;               // (r&3)==(cr&3)
      CP_ASYNC16(aS + (uint32_t)(r * ROW_BYTES) + dquad,
                 abase + (size_t)r * Kdim + k0 + cq * 8);
      CP_ASYNC16(bS + (uint32_t)(r * ROW_BYTES) + dquad,
                 wbase + (size_t)r * Kdim + k0 + cq * 8);
    }
  };

  issue(0, 0); CP_COMMIT();
  issue(1, STAGE_BYTES); CP_COMMIT();

  const int wRow = wid >> 1;                   // 0..3 -> M*32
  const int wCol = wid & 1;                    // 0..1 -> N*64
  const int g    = lane >> 2;
  const int tig  = lane & 3;

  // per-k16 8B-slot byte offsets (u = 0,1)
  uint32_t off_u[2];
  #pragma unroll
  for (int u = 0; u < 2; ++u)
    off_u[u] = (uint32_t)((((4*u + tig) + 4*(g & 3)) & 15) * 8);

  const uint32_t awb = dyn0 + (uint32_t)((wRow*32 + g) * ROW_BYTES);
  const uint32_t bwb = dyn0 + TILE_BYTES + (uint32_t)((wCol*64 + g) * ROW_BYTES);

  float acc[2][8][4];
  #pragma unroll
  for (int mf = 0; mf < 2; ++mf)
    #pragma unroll
    for (int nf = 0; nf < 8; ++nf)
      #pragma unroll
      for (int q = 0; q < 4; ++q) acc[mf][nf][q] = 0.f;

  uint32_t stoff_c = 0, stoff_n = 2u * STAGE_BYTES;
  for (int c = 0; c < nch; ++c) {
    CP_WAIT(STAGES - 2);
    __syncthreads();
    if (c + STAGES - 1 < nch) issue(c + STAGES - 1, stoff_n);
    CP_COMMIT();

    const uint32_t aw = awb + stoff_c;
    const uint32_t bw = bwb + stoff_c;

    #pragma unroll
    for (int u = 0; u < 2; ++u) {              // two k16 steps per chunk
      const uint32_t au = aw + off_u[u];
      const uint32_t bu = bw + off_u[u];
      uint32_t a0,a1,a2,a3, e0,e1,e2,e3;
      LDS64(a0, a2, au);                       // row wRow*32+g   : k-lo, k-hi
      LDS64(a1, a3, au + 8*ROW_BYTES);         // row +8
      LDS64(e0, e2, au + 16*ROW_BYTES);        // mf=1
      LDS64(e1, e3, au + 24*ROW_BYTES);
      #pragma unroll
      for (int nf = 0; nf < 8; ++nf) {
        uint32_t b0, b1;
        LDS64(b0, b1, bu + nf*(8*ROW_BYTES));  // col wCol*64+nf*8+g
        mma_f16(acc[0][nf][0], acc[0][nf][1], acc[0][nf][2], acc[0][nf][3],
                a0, a1, a2, a3, b0, b1);
        mma_f16(acc[1][nf][0], acc[1][nf][1], acc[1][nf][2], acc[1][nf][3],
                e0, e1, e2, e3, b0, b1);
      }
    }
    stoff_c += STAGE_BYTES; if (stoff_c == STAGES*STAGE_BYTES) stoff_c = 0;
    stoff_n += STAGE_BYTES; if (stoff_n == STAGES*STAGE_BYTES) stoff_n = 0;
  }

  // epilogue: bias, natural f32 writes
  const float* bptr = bias + (size_t)e * Ndim + n0;
  #pragma unroll
  for (int mf = 0; mf < 2; ++mf) {
    #pragma unroll
    for (int half = 0; half < 2; ++half) {
      const int rl = wRow * 32 + mf * 16 + g + half * 8;
      if (rl < valid) {
        float* orow = out + (size_t)(m0 + rl) * Ndim + n0;
        #pragma unroll
        for (int nf = 0; nf < 8; ++nf) {
          const int col = wCol * 64 + nf * 8 + 2*tig;
          float2 v;
          v.x = acc[mf][nf][half*2 + 0] + bptr[col];
          v.y = acc[mf][nf][half*2 + 1] + bptr[col + 1];
          *(float2*)(orow + col) = v;
        }
      }
    }
  }
}

// ------------------------- combine + residual + LN ----------------------
__global__ void __launch_bounds__(256) moe_final_ln(const float* __restrict__ x,
                                                    const float* __restrict__ lnw,
                                                    const float* __restrict__ lnb,
                                                    float* __restrict__ out){
  __shared__ float ps[8], ps2[8], s_mu, s_rs;
  const int t  = blockIdx.x;
  const int r0 = g_token_row[2*t], r1 = g_token_row[2*t+1];
  const float w0 = g_topk_w[2*t],  w1 = g_topk_w[2*t+1];
  const float* xr = x      + (size_t)t  * HDIM;
  const float* a0 = g_out2 + (size_t)r0 * HDIM;
  const float* a1 = g_out2 + (size_t)r1 * HDIM;
  float v[4]; float s = 0.f, s2 = 0.f;
  #pragma unroll
  for (int j = 0; j < 4; ++j) {
    int h = threadIdx.x + 256 * j;
    float val = xr[h] + w0 * a0[h] + w1 * a1[h];
    v[j] = val; s += val; s2 += val * val;
  }
  #pragma unroll
  for (int o = 16; o; o >>= 1) {
    s  += __shfl_xor_sync(0xffffffffu, s,  o);
    s2 += __shfl_xor_sync(0xffffffffu, s2, o);
  }
  const int wd = threadIdx.x >> 5, lane = threadIdx.x & 31;
  if (lane == 0) { ps[wd] = s; ps2[wd] = s2; }
  __syncthreads();
  if (threadIdx.x == 0) {
    float S = 0.f, S2 = 0.f;
    #pragma unroll
    for (int i = 0; i < 8; ++i) { S += ps[i]; S2 += ps2[i]; }
    float mu  = S * (1.f / HDIM);
    float var = S2 * (1.f / HDIM) - mu * mu;
    s_mu = mu; s_rs = rsqrtf(var + 1e-12f);
  }
  __syncthreads();
  const float mu = s_mu, rs = s_rs;
  #pragma unroll
  for (int j = 0; j < 4; ++j) {
    int h = threadIdx.x + 256 * j;
    out[(size_t)t * HDIM + h] = (v[j] - mu) * rs * lnw[h] + lnb[h];
  }
}

// ------------------------- launch ---------------------------------------
extern "C" void kernel_launch(void* const* d_in, const int* in_sizes, int n_in,
                              void* d_out, int out_size){
  (void)in_sizes; (void)n_in; (void)out_size;
  const float* x   = (const float*)d_in[0];
  const float* rw  = (const float*)d_in[1];
  const float* rb  = (const float*)d_in[2];
  const float* w1  = (const float*)d_in[3];
  const float* b1  = (const float*)d_in[4];
  const float* w2  = (const float*)d_in[5];
  const float* b2  = (const float*)d_in[6];
  const float* lnw = (const float*)d_in[7];
  const float* lnb = (const float*)d_in[8];
  float* out = (float*)d_out;

  float*  w1r; cudaGetSymbolAddress((void**)&w1r, g_w1r);
  __half* w2h; cudaGetSymbolAddress((void**)&w2h, g_w2h);
  float*  xrp; cudaGetSymbolAddress((void**)&xrp, g_xr);
  __half* y1p; cudaGetSymbolAddress((void**)&y1p, g_y1h);
  float*  o2p; cudaGetSymbolAddress((void**)&o2p, g_out2);

  cudaFuncSetAttribute(moe_gemm1, cudaFuncAttributeMaxDynamicSharedMemorySize, DYN_SMEM);
  cudaFuncSetAttribute(moe_gemm2, cudaFuncAttributeMaxDynamicSharedMemorySize, DYN_SMEM);

  const int N8  = (int)((size_t)NEXP * FFDIM * HDIM / 8);
  const int N16 = (int)((size_t)NEXP * FFDIM * HDIM / 16);

  round_w1_kernel<<<4096, 256>>>((const float4*)w1, (uint4*)w1r, N8);      // 0 (+zero cnt)
  moe_router<<<NTOK/4, 128>>>(x, rw, rb);                                   // 1
  routing_finalize<<<1, 1024>>>();                                         // 2
  moe_gemm1<<<dim3(NEXP*MT_CAP, FFDIM/128), GEMM_THREADS, DYN_SMEM>>>(
      xrp, w1r, b1, y1p, HDIM, FFDIM);                                     // 3: GEMM1 (profiled)
  round_w2_kernel<<<4096, 256>>>((const float4*)w2, (uint4*)w2h, N16);     // 4
  moe_gemm2<<<dim3(NEXP*MT_CAP, HDIM/128), GEMM_THREADS, DYN_SMEM>>>(
      y1p, w2h, b2, o2p, FFDIM, HDIM);                                     // 5: GEMM2 fp16
  moe_final_ln<<<NTOK, 256>>>(x, lnw, lnb, out);                           // 6
}

// round 12
// speedup vs baseline: 1.8493x; 1.3568x over previous
#include <cuda_runtime.h>
#include <cuda_fp16.h>
#include <cstdint>

#define NTOK   8192
#define HDIM   1024
#define FFDIM  4096
#define NEXP   8
#define NROWS  (NTOK*2)
#define MT_CAP 64                  // max 128-row M-tiles per expert
#define GEMM_THREADS 256
#define ROW_BYTES 128              // 64B fp16 data per row (swizzled quads)
#define TILE_BYTES (128*ROW_BYTES) // 16 KB per operand per stage
#define STAGE_BYTES (2*TILE_BYTES) // 32 KB (A + B)
#define STAGES 3
#define DYN_SMEM (STAGES*STAGE_BYTES)   // 96 KB

// ------------------------- device scratch (static) ----------------------
__device__ int    g_cnt[NEXP];
__device__ int    g_off[NEXP];
__device__ int    g_topk_e[NTOK*2];
__device__ float  g_topk_w[NTOK*2];
__device__ int    g_rows_token[NROWS];             // row -> token
__device__ int    g_token_row[NTOK*2];             // token,k -> row
__device__ __half g_w1h[(size_t)NEXP*FFDIM*HDIM];  // fp16+perm16 w1
__device__ __half g_w2h[(size_t)NEXP*HDIM*FFDIM];  // fp16+perm16 w2
__device__ __half g_xh[(size_t)NTOK*HDIM];         // fp16+perm16 x (token order)
__device__ __half g_y1h[(size_t)(NROWS+128)*FFDIM];// fp16+perm16 intermediate
__device__ float  g_out2[(size_t)NROWS*HDIM];      // expert outputs (natural)

// ------------------------- PTX helpers ----------------------------------
__device__ __forceinline__ uint32_t smem_u32(const void* p){
  uint32_t a;
  asm("{ .reg .u64 t; cvta.to.shared.u64 t, %1; cvt.u32.u64 %0, t; }" : "=r"(a) : "l"(p));
  return a;
}
#define CP_ASYNC16(dst, src) \
  asm volatile("cp.async.cg.shared.global [%0], [%1], 16;" :: "r"(dst), "l"(src) : "memory")
#define CP_COMMIT() asm volatile("cp.async.commit_group;" ::: "memory")
#define CP_WAIT(N)  asm volatile("cp.async.wait_group %0;" :: "n"(N) : "memory")
#define LDS64(lo, hi, addr) \
  asm volatile("ld.shared.v2.b32 {%0,%1}, [%2];" : "=r"(lo), "=r"(hi) : "r"(addr))

__device__ __forceinline__ void mma_f16(float& c0, float& c1, float& c2, float& c3,
                                        uint32_t a0, uint32_t a1, uint32_t a2, uint32_t a3,
                                        uint32_t b0, uint32_t b1){
  asm volatile(
    "mma.sync.aligned.m16n8k16.row.col.f32.f16.f16.f32 "
    "{%0,%1,%2,%3}, {%4,%5,%6,%7}, {%8,%9}, {%0,%1,%2,%3};"
    : "+f"(c0), "+f"(c1), "+f"(c2), "+f"(c3)
    : "r"(a0), "r"(a1), "r"(a2), "r"(a3), "r"(b0), "r"(b1));
}
__device__ __forceinline__ float gelu_exact(float v){
  return 0.5f * v * (1.0f + erff(v * 0.70710678118654752f));
}
__device__ __forceinline__ uint32_t h2pack(float a, float b){
  __half2 h = __floats2half2_rn(a, b);
  return *(uint32_t*)&h;
}

// fp16 convert + K-permute one aligned 16-float group:
// pos(8h+2t+b) = 4t+2h+b  (so a thread's k16 fragment = 8 contiguous bytes)
__device__ __forceinline__ void perm16_h(const float4* s4, uint4* d2){
  float4 a = s4[0], b = s4[1], c = s4[2], d = s4[3];
  uint4 o0, o1;
  o0.x = h2pack(a.x, a.y);   // pos 0,1   <- f0,f1
  o0.y = h2pack(c.x, c.y);   // pos 2,3   <- f8,f9
  o0.z = h2pack(a.z, a.w);   // pos 4,5   <- f2,f3
  o0.w = h2pack(c.z, c.w);   // pos 6,7   <- f10,f11
  o1.x = h2pack(b.x, b.y);   // pos 8,9   <- f4,f5
  o1.y = h2pack(d.x, d.y);   // pos 10,11 <- f12,f13
  o1.z = h2pack(b.z, b.w);   // pos 12,13 <- f6,f7
  o1.w = h2pack(d.z, d.w);   // pos 14,15 <- f14,f15
  d2[0] = o0; d2[1] = o1;
}

// ------------------------- prep: BOTH weights fp16+perm16 (+zero cnt) ---
__global__ void __launch_bounds__(256) round_wh_kernel(const float4* __restrict__ s1,
                                                       uint4* __restrict__ d1,
                                                       const float4* __restrict__ s2,
                                                       uint4* __restrict__ d2, int n16){
  if (blockIdx.x == 0 && threadIdx.x < NEXP) g_cnt[threadIdx.x] = 0;
  int i = blockIdx.x * 256 + threadIdx.x;
  const int stride = gridDim.x * 256;
  for (; i < 2 * n16; i += stride) {
    const float4* src = (i < n16) ? s1 : s2;
    uint4*       dst  = (i < n16) ? d1 : d2;
    const int j = (i < n16) ? i : i - n16;
    uint4 o[2];
    perm16_h(src + 4*j, o);
    dst[2*j] = o[0]; dst[2*j+1] = o[1];
  }
}

// ------------------------- router (+ write fp16/perm16 x) ---------------
__global__ void __launch_bounds__(128) moe_router(const float* __restrict__ x,
                                                  const float* __restrict__ rw,
                                                  const float* __restrict__ rb){
  const int lane  = threadIdx.x & 31;
  const int token = blockIdx.x * 4 + (threadIdx.x >> 5);
  const float* xr = x + (size_t)token * HDIM;
  float acc[NEXP];
  #pragma unroll
  for (int e = 0; e < NEXP; ++e) acc[e] = 0.f;
  for (int h = lane; h < HDIM; h += 32) {
    float xv = xr[h];
    #pragma unroll
    for (int e = 0; e < NEXP; ++e) acc[e] += xv * rw[e * HDIM + h];
  }
  #pragma unroll
  for (int e = 0; e < NEXP; ++e) {
    #pragma unroll
    for (int o = 16; o; o >>= 1) acc[e] += __shfl_xor_sync(0xffffffffu, acc[e], o);
  }
  if (lane == 0) {
    float v[NEXP];
    #pragma unroll
    for (int e = 0; e < NEXP; ++e) v[e] = acc[e] + rb[e];
    int e0 = 0; float v0 = v[0];
    #pragma unroll
    for (int e = 1; e < NEXP; ++e) if (v[e] > v0) { v0 = v[e]; e0 = e; }
    int e1 = (e0 == 0) ? 1 : 0; float v1 = v[e1];
    #pragma unroll
    for (int e = 0; e < NEXP; ++e) if (e != e0 && v[e] > v1) { v1 = v[e]; e1 = e; }
    float t  = expf(v1 - v0);
    float w0 = 1.f / (1.f + t);
    g_topk_e[2*token]   = e0;  g_topk_e[2*token+1] = e1;
    g_topk_w[2*token]   = w0;  g_topk_w[2*token+1] = t * w0;
    atomicAdd(&g_cnt[e0], 1);  atomicAdd(&g_cnt[e1], 1);
  }
  // fp16 + perm16 copy of this token's row (64 16-groups, 2 per lane)
  const float4* srcv = (const float4*)xr;
  uint4* dstv = (uint4*)(g_xh + (size_t)token * HDIM);
  #pragma unroll
  for (int j = 0; j < 2; ++j) {
    int gi = lane + 32 * j;
    uint4 o[2];
    perm16_h(srcv + 4*gi, o);
    dstv[2*gi] = o[0]; dstv[2*gi+1] = o[1];
  }
}

// ------------------------- offsets + scatter (single block) -------------
__global__ void __launch_bounds__(1024) routing_finalize(){
  __shared__ int s_cur[NEXP];
  if (threadIdx.x == 0) {
    int o = 0;
    #pragma unroll
    for (int e = 0; e < NEXP; ++e) { g_off[e] = o; s_cur[e] = o; o += g_cnt[e]; }
  }
  __syncthreads();
  for (int t = threadIdx.x; t < NTOK; t += 1024) {
    #pragma unroll
    for (int k = 0; k < 2; ++k) {
      int e = g_topk_e[2*t + k];
      int pos = atomicAdd(&s_cur[e], 1);
      g_rows_token[pos]  = t;
      g_token_row[2*t+k] = pos;
    }
  }
}

// ------------------------- unified fp16 m16n8k16 GEMM -------------------
// K stored perm16 (pos(8h+2t+b)=4t+2h+b) so each thread's k16 fragment is
// one LDS64. Smem: 64B data in 128B rows; logical 16B quad q at physical
// (q + 2*(row&3)) & 3... stored via dquad; read slot (4u+tig+4*(g&3))&15.
// FIRST: gather A rows via token list; epilogue gelu + fp16/perm16 out.
// else : contiguous A; epilogue bias + natural f32 out.
template<bool FIRST>
__global__ void __launch_bounds__(GEMM_THREADS, 2)
moe_gemm_h(const __half* __restrict__ A, const __half* __restrict__ W,
           const float* __restrict__ bias, void* __restrict__ outv,
           int Kdim, int Ndim)
{
  const int tid  = threadIdx.x;
  const int lane = tid & 31;
  const int wid  = tid >> 5;
  const int e    = blockIdx.x >> 6;
  const int mt   = blockIdx.x & (MT_CAP - 1);
  const int cnt  = g_cnt[e];
  if (mt * 128 >= cnt) return;
  const int m0    = g_off[e] + mt * 128;
  const int valid = min(128, cnt - mt * 128);
  const int n0    = blockIdx.y * 128;

  __shared__ const __half* s_aptr[128];
  extern __shared__ __align__(16) char dsm[];
  const uint32_t dyn0 = smem_u32(dsm);

  if (FIRST && tid < 128) {
    int r   = tid;
    int tok = g_rows_token[m0 + min(r, valid - 1)];
    s_aptr[r] = A + (size_t)tok * Kdim;
  }
  __syncthreads();

  const __half* abase = A + (size_t)m0 * Kdim;          // !FIRST path
  const __half* wbase = W + ((size_t)e * Ndim + n0) * Kdim;
  const int nch = Kdim >> 5;                   // 32 halves per chunk

  const int cr = tid >> 2;                     // base row 0..63
  const int cq = tid & 3;                      // logical 16B quad (0..3)
  const uint32_t dquad = (uint32_t)(((cq + 2*(cr & 3)) & 7) * 16);

  auto issue = [&](int c, uint32_t stoff){
    const uint32_t aS = dyn0 + stoff;
    const uint32_t bS = aS + TILE_BYTES;
    const int k0 = c << 5;                     // halves
    #pragma unroll
    for (int j = 0; j < 2; ++j) {
      const int r = cr + 64 * j;               // (r&3)==(cr&3)
      const __half* srcA = FIRST ? (s_aptr[r] + k0 + cq * 8)
                                 : (abase + (size_t)r * Kdim + k0 + cq * 8);
      CP_ASYNC16(aS + (uint32_t)(r * ROW_BYTES) + dquad, srcA);
      CP_ASYNC16(bS + (uint32_t)(r * ROW_BYTES) + dquad,
                 wbase + (size_t)r * Kdim + k0 + cq * 8);
    }
  };

  issue(0, 0); CP_COMMIT();
  issue(1, STAGE_BYTES); CP_COMMIT();

  const int wRow = wid >> 1;                   // 0..3 -> M*32
  const int wCol = wid & 1;                    // 0..1 -> N*64
  const int g    = lane >> 2;
  const int tig  = lane & 3;

  // per-k16 8B-slot byte offsets (u = 0,1)
  uint32_t off_u[2];
  #pragma unroll
  for (int u = 0; u < 2; ++u)
    off_u[u] = (uint32_t)((((4*u + tig) + 4*(g & 3)) & 15) * 8);

  const uint32_t awb = dyn0 + (uint32_t)((wRow*32 + g) * ROW_BYTES);
  const uint32_t bwb = dyn0 + TILE_BYTES + (uint32_t)((wCol*64 + g) * ROW_BYTES);

  float acc[2][8][4];
  #pragma unroll
  for (int mf = 0; mf < 2; ++mf)
    #pragma unroll
    for (int nf = 0; nf < 8; ++nf)
      #pragma unroll
      for (int q = 0; q < 4; ++q) acc[mf][nf][q] = 0.f;

  uint32_t stoff_c = 0, stoff_n = 2u * STAGE_BYTES;
  for (int c = 0; c < nch; ++c) {
    CP_WAIT(STAGES - 2);
    __syncthreads();
    if (c + STAGES - 1 < nch) issue(c + STAGES - 1, stoff_n);
    CP_COMMIT();

    const uint32_t aw = awb + stoff_c;
    const uint32_t bw = bwb + stoff_c;

    #pragma unroll
    for (int u = 0; u < 2; ++u) {              // two k16 steps per chunk
      const uint32_t au = aw + off_u[u];
      const uint32_t bu = bw + off_u[u];
      uint32_t a0,a1,a2,a3, e0,e1,e2,e3;
      LDS64(a0, a2, au);                       // row wRow*32+g : k-lo, k-hi
      LDS64(a1, a3, au + 8*ROW_BYTES);         // row +8
      LDS64(e0, e2, au + 16*ROW_BYTES);        // mf=1
      LDS64(e1, e3, au + 24*ROW_BYTES);
      #pragma unroll
      for (int nf = 0; nf < 8; ++nf) {
        uint32_t b0, b1;
        LDS64(b0, b1, bu + nf*(8*ROW_BYTES));  // col wCol*64+nf*8+g
        mma_f16(acc[0][nf][0], acc[0][nf][1], acc[0][nf][2], acc[0][nf][3],
                a0, a1, a2, a3, b0, b1);
        mma_f16(acc[1][nf][0], acc[1][nf][1], acc[1][nf][2], acc[1][nf][3],
                e0, e1, e2, e3, b0, b1);
      }
    }
    stoff_c += STAGE_BYTES; if (stoff_c == STAGES*STAGE_BYTES) stoff_c = 0;
    stoff_n += STAGE_BYTES; if (stoff_n == STAGES*STAGE_BYTES) stoff_n = 0;
  }

  // ---------------- epilogue ---------------------------------------------
  const float* bptr = bias + (size_t)e * Ndim + n0;
  #pragma unroll
  for (int mf = 0; mf < 2; ++mf) {
    #pragma unroll
    for (int half = 0; half < 2; ++half) {
      const int rl = wRow * 32 + mf * 16 + g + half * 8;
      if (rl < valid) {
        if (FIRST) {
          // gelu + fp16 round + perm16 scatter:
          // logical cols c0 = wCol*64+nf*8+2tig, c0+1 -> half2 at
          //   (wCol*4 + (nf>>1))*16 + 4*tig + 2*(nf&1)
          __half* orow = (__half*)outv + (size_t)(m0 + rl) * Ndim + n0;
          #pragma unroll
          for (int nf = 0; nf < 8; ++nf) {
            const int nbase = wCol * 64 + nf * 8;
            float v0 = acc[mf][nf][half*2 + 0] + bptr[nbase + 2*tig];
            float v1 = acc[mf][nf][half*2 + 1] + bptr[nbase + 2*tig + 1];
            v0 = gelu_exact(v0); v1 = gelu_exact(v1);
            const int ocol = (wCol*4 + (nf >> 1))*16 + 4*tig + 2*(nf & 1);
            __half2 hv = __floats2half2_rn(v0, v1);
            *(__half2*)(orow + ocol) = hv;
          }
        } else {
          float* orow = (float*)outv + (size_t)(m0 + rl) * Ndim + n0;
          #pragma unroll
          for (int nf = 0; nf < 8; ++nf) {
            const int col = wCol * 64 + nf * 8 + 2*tig;
            float2 v;
            v.x = acc[mf][nf][half*2 + 0] + bptr[col];
            v.y = acc[mf][nf][half*2 + 1] + bptr[col + 1];
            *(float2*)(orow + col) = v;
          }
        }
      }
    }
  }
}

// ------------------------- combine + residual + LN ----------------------
__global__ void __launch_bounds__(256) moe_final_ln(const float* __restrict__ x,
                                                    const float* __restrict__ lnw,
                                                    const float* __restrict__ lnb,
                                                    float* __restrict__ out){
  __shared__ float ps[8], ps2[8], s_mu, s_rs;
  const int t  = blockIdx.x;
  const int r0 = g_token_row[2*t], r1 = g_token_row[2*t+1];
  const float w0 = g_topk_w[2*t],  w1 = g_topk_w[2*t+1];
  const float* xr = x      + (size_t)t  * HDIM;
  const float* a0 = g_out2 + (size_t)r0 * HDIM;
  const float* a1 = g_out2 + (size_t)r1 * HDIM;
  float v[4]; float s = 0.f, s2 = 0.f;
  #pragma unroll
  for (int j = 0; j < 4; ++j) {
    int h = threadIdx.x + 256 * j;
    float val = xr[h] + w0 * a0[h] + w1 * a1[h];
    v[j] = val; s += val; s2 += val * val;
  }
  #pragma unroll
  for (int o = 16; o; o >>= 1) {
    s  += __shfl_xor_sync(0xffffffffu, s,  o);
    s2 += __shfl_xor_sync(0xffffffffu, s2, o);
  }
  const int wd = threadIdx.x >> 5, lane = threadIdx.x & 31;
  if (lane == 0) { ps[wd] = s; ps2[wd] = s2; }
  __syncthreads();
  if (threadIdx.x == 0) {
    float S = 0.f, S2 = 0.f;
    #pragma unroll
    for (int i = 0; i < 8; ++i) { S += ps[i]; S2 += ps2[i]; }
    float mu  = S * (1.f / HDIM);
    float var = S2 * (1.f / HDIM) - mu * mu;
    s_mu = mu; s_rs = rsqrtf(var + 1e-12f);
  }
  __syncthreads();
  const float mu = s_mu, rs = s_rs;
  #pragma unroll
  for (int j = 0; j < 4; ++j) {
    int h = threadIdx.x + 256 * j;
    out[(size_t)t * HDIM + h] = (v[j] - mu) * rs * lnw[h] + lnb[h];
  }
}

// ------------------------- launch ---------------------------------------
extern "C" void kernel_launch(void* const* d_in, const int* in_sizes, int n_in,
                              void* d_out, int out_size){
  (void)in_sizes; (void)n_in; (void)out_size;
  const float* x   = (const float*)d_in[0];
  const float* rw  = (const float*)d_in[1];
  const float* rb  = (const float*)d_in[2];
  const float* w1  = (const float*)d_in[3];
  const float* b1  = (const float*)d_in[4];
  const float* w2  = (const float*)d_in[5];
  const float* b2  = (const float*)d_in[6];
  const float* lnw = (const float*)d_in[7];
  const float* lnb = (const float*)d_in[8];
  float* out = (float*)d_out;

  __half* w1h; cudaGetSymbolAddress((void**)&w1h, g_w1h);
  __half* w2h; cudaGetSymbolAddress((void**)&w2h, g_w2h);
  __half* xhp; cudaGetSymbolAddress((void**)&xhp, g_xh);
  __half* y1p; cudaGetSymbolAddress((void**)&y1p, g_y1h);
  float*  o2p; cudaGetSymbolAddress((void**)&o2p, g_out2);

  cudaFuncSetAttribute(moe_gemm_h<true >, cudaFuncAttributeMaxDynamicSharedMemorySize, DYN_SMEM);
  cudaFuncSetAttribute(moe_gemm_h<false>, cudaFuncAttributeMaxDynamicSharedMemorySize, DYN_SMEM);

  const int N16 = (int)((size_t)NEXP * FFDIM * HDIM / 16);

  round_wh_kernel<<<8192, 256>>>((const float4*)w1, (uint4*)w1h,
                                 (const float4*)w2, (uint4*)w2h, N16);     // 0 (+zero cnt)
  moe_router<<<NTOK/4, 128>>>(x, rw, rb);                                   // 1
  routing_finalize<<<1, 1024>>>();                                         // 2
  moe_gemm_h<true ><<<dim3(NEXP*MT_CAP, FFDIM/128), GEMM_THREADS, DYN_SMEM>>>(
      xhp, w1h, b1, y1p, HDIM, FFDIM);                                     // 3: GEMM1 (profiled)
  moe_gemm_h<false><<<dim3(NEXP*MT_CAP, HDIM/128), GEMM_THREADS, DYN_SMEM>>>(
      y1p, w2h, b2, o2p, FFDIM, HDIM);                                     // 4: GEMM2
  moe_final_ln<<<NTOK, 256>>>(x, lnw, lnb, out);                           // 5
}

// round 14
// speedup vs baseline: 1.8812x; 1.0172x over previous
#include <cuda_runtime.h>
#include <cuda_fp16.h>
#include <cstdint>

#define NTOK   8192
#define HDIM   1024
#define FFDIM  4096
#define NEXP   8
#define NROWS  (NTOK*2)
#define MAXTILES 160               // >= 8 + NROWS/128 = 136
#define GEMM_THREADS 256
#define ROW_BYTES 128              // 64 halves per row, fully packed (BK=64)
#define TILE_BYTES (128*ROW_BYTES) // 16 KB per operand per stage
#define STAGE_BYTES (2*TILE_BYTES) // 32 KB (A + B)
#define STAGES 3
#define DYN_SMEM (STAGES*STAGE_BYTES)   // 96 KB

// ------------------------- device scratch (static) ----------------------
__device__ int    g_cnt[NEXP];
__device__ int    g_off[NEXP];
__device__ int    g_topk_e[NTOK*2];
__device__ float  g_topk_w[NTOK*2];
__device__ int    g_rows_token[NROWS];             // row -> token
__device__ int    g_token_row[NTOK*2];             // token,k -> row
__device__ int    g_tile_e[MAXTILES];
__device__ int    g_tile_m0[MAXTILES];
__device__ int    g_tile_valid[MAXTILES];
__device__ int    g_ntiles;
__device__ __half g_w1h[(size_t)NEXP*FFDIM*HDIM];  // fp16+perm16 w1
__device__ __half g_w2h[(size_t)NEXP*HDIM*FFDIM];  // fp16+perm16 w2
__device__ __half g_xh[(size_t)NTOK*HDIM];         // fp16+perm16 x (token order)
__device__ __half g_y1h[(size_t)(NROWS+128)*FFDIM];// fp16+perm16 intermediate
__device__ float  g_out2[(size_t)NROWS*HDIM];      // expert outputs (natural)

// ------------------------- PTX helpers ----------------------------------
__device__ __forceinline__ uint32_t smem_u32(const void* p){
  uint32_t a;
  asm("{ .reg .u64 t; cvta.to.shared.u64 t, %1; cvt.u32.u64 %0, t; }" : "=r"(a) : "l"(p));
  return a;
}
#define CP_ASYNC16(dst, src) \
  asm volatile("cp.async.cg.shared.global [%0], [%1], 16;" :: "r"(dst), "l"(src) : "memory")
#define CP_COMMIT() asm volatile("cp.async.commit_group;" ::: "memory")
#define CP_WAIT(N)  asm volatile("cp.async.wait_group %0;" :: "n"(N) : "memory")
#define LDS64(lo, hi, addr) \
  asm volatile("ld.shared.v2.b32 {%0,%1}, [%2];" : "=r"(lo), "=r"(hi) : "r"(addr))

__device__ __forceinline__ void mma_f16(float& c0, float& c1, float& c2, float& c3,
                                        uint32_t a0, uint32_t a1, uint32_t a2, uint32_t a3,
                                        uint32_t b0, uint32_t b1){
  asm volatile(
    "mma.sync.aligned.m16n8k16.row.col.f32.f16.f16.f32 "
    "{%0,%1,%2,%3}, {%4,%5,%6,%7}, {%8,%9}, {%0,%1,%2,%3};"
    : "+f"(c0), "+f"(c1), "+f"(c2), "+f"(c3)
    : "r"(a0), "r"(a1), "r"(a2), "r"(a3), "r"(b0), "r"(b1));
}
__device__ __forceinline__ float gelu_exact(float v){
  return 0.5f * v * (1.0f + erff(v * 0.70710678118654752f));
}
__device__ __forceinline__ uint32_t h2pack(float a, float b){
  __half2 h = __floats2half2_rn(a, b);
  return *(uint32_t*)&h;
}

// fp16 convert + K-permute one aligned 16-float group:
// pos(8h+2t+b) = 4t+2h+b  (so a thread's k16 fragment = 8 contiguous bytes)
__device__ __forceinline__ void perm16_h(const float4* s4, uint4* d2){
  float4 a = s4[0], b = s4[1], c = s4[2], d = s4[3];
  uint4 o0, o1;
  o0.x = h2pack(a.x, a.y);   // pos 0,1   <- f0,f1
  o0.y = h2pack(c.x, c.y);   // pos 2,3   <- f8,f9
  o0.z = h2pack(a.z, a.w);   // pos 4,5   <- f2,f3
  o0.w = h2pack(c.z, c.w);   // pos 6,7   <- f10,f11
  o1.x = h2pack(b.x, b.y);   // pos 8,9   <- f4,f5
  o1.y = h2pack(d.x, d.y);   // pos 10,11 <- f12,f13
  o1.z = h2pack(b.z, b.w);   // pos 12,13 <- f6,f7
  o1.w = h2pack(d.z, d.w);   // pos 14,15 <- f14,f15
  d2[0] = o0; d2[1] = o1;
}

// ------------------------- prep: BOTH weights fp16+perm16 (+zero cnt) ---
__global__ void __launch_bounds__(256) round_wh_kernel(const float4* __restrict__ s1,
                                                       uint4* __restrict__ d1,
                                                       const float4* __restrict__ s2,
                                                       uint4* __restrict__ d2, int n16){
  if (blockIdx.x == 0 && threadIdx.x < NEXP) g_cnt[threadIdx.x] = 0;
  int i = blockIdx.x * 256 + threadIdx.x;
  const int stride = gridDim.x * 256;
  for (; i < 2 * n16; i += stride) {
    const float4* src = (i < n16) ? s1 : s2;
    uint4*       dst  = (i < n16) ? d1 : d2;
    const int j = (i < n16) ? i : i - n16;
    uint4 o[2];
    perm16_h(src + 4*j, o);
    dst[2*j] = o[0]; dst[2*j+1] = o[1];
  }
}

// ------------------------- router (+ write fp16/perm16 x) ---------------
__global__ void __launch_bounds__(128) moe_router(const float* __restrict__ x,
                                                  const float* __restrict__ rw,
                                                  const float* __restrict__ rb){
  const int lane  = threadIdx.x & 31;
  const int token = blockIdx.x * 4 + (threadIdx.x >> 5);
  const float* xr = x + (size_t)token * HDIM;
  float acc[NEXP];
  #pragma unroll
  for (int e = 0; e < NEXP; ++e) acc[e] = 0.f;
  for (int h = lane; h < HDIM; h += 32) {
    float xv = xr[h];
    #pragma unroll
    for (int e = 0; e < NEXP; ++e) acc[e] += xv * rw[e * HDIM + h];
  }
  #pragma unroll
  for (int e = 0; e < NEXP; ++e) {
    #pragma unroll
    for (int o = 16; o; o >>= 1) acc[e] += __shfl_xor_sync(0xffffffffu, acc[e], o);
  }
  if (lane == 0) {
    float v[NEXP];
    #pragma unroll
    for (int e = 0; e < NEXP; ++e) v[e] = acc[e] + rb[e];
    int e0 = 0; float v0 = v[0];
    #pragma unroll
    for (int e = 1; e < NEXP; ++e) if (v[e] > v0) { v0 = v[e]; e0 = e; }
    int e1 = (e0 == 0) ? 1 : 0; float v1 = v[e1];
    #pragma unroll
    for (int e = 0; e < NEXP; ++e) if (e != e0 && v[e] > v1) { v1 = v[e]; e1 = e; }
    float t  = expf(v1 - v0);
    float w0 = 1.f / (1.f + t);
    g_topk_e[2*token]   = e0;  g_topk_e[2*token+1] = e1;
    g_topk_w[2*token]   = w0;  g_topk_w[2*token+1] = t * w0;
    atomicAdd(&g_cnt[e0], 1);  atomicAdd(&g_cnt[e1], 1);
  }
  // fp16 + perm16 copy of this token's row (64 16-groups, 2 per lane)
  const float4* srcv = (const float4*)xr;
  uint4* dstv = (uint4*)(g_xh + (size_t)token * HDIM);
  #pragma unroll
  for (int j = 0; j < 2; ++j) {
    int gi = lane + 32 * j;
    uint4 o[2];
    perm16_h(srcv + 4*gi, o);
    dstv[2*gi] = o[0]; dstv[2*gi+1] = o[1];
  }
}

// ------------------------- offsets + scatter + tile list ----------------
__global__ void __launch_bounds__(1024) routing_finalize(){
  __shared__ int s_cur[NEXP];
  if (threadIdx.x == 0) {
    int o = 0, nt = 0;
    #pragma unroll
    for (int e = 0; e < NEXP; ++e) {
      g_off[e] = o; s_cur[e] = o;
      const int ce = g_cnt[e];
      for (int mt = 0; mt * 128 < ce; ++mt) {
        g_tile_e[nt]     = e;
        g_tile_m0[nt]    = o + mt * 128;
        g_tile_valid[nt] = min(128, ce - mt * 128);
        ++nt;
      }
      o += ce;
    }
    g_ntiles = nt;
  }
  __syncthreads();
  for (int t = threadIdx.x; t < NTOK; t += 1024) {
    #pragma unroll
    for (int k = 0; k < 2; ++k) {
      int e = g_topk_e[2*t + k];
      int pos = atomicAdd(&s_cur[e], 1);
      g_rows_token[pos]  = t;
      g_token_row[2*t+k] = pos;
    }
  }
}

// ------------------------- unified fp16 m16n8k16 GEMM (BK=64) -----------
// K stored perm16; smem rows fully packed: 64 halves (4 k16 groups) per
// 128B row. Store: quad cq 0..7 at phys ((cq+2*(row&3))&7)*16. Read: 8B
// slot (4u+tig+4*(g&3))&15, u = 0..3. Conflict-free both sides.
// FIRST: gather A rows via token list; epilogue gelu + fp16/perm16 out.
template<bool FIRST>
__global__ void __launch_bounds__(GEMM_THREADS, 2)
moe_gemm_h(const __half* __restrict__ A, const __half* __restrict__ W,
           const float* __restrict__ bias, void* __restrict__ outv,
           int Kdim, int Ndim)
{
  const int ti = blockIdx.x;
  if (ti >= g_ntiles) return;
  const int tid  = threadIdx.x;
  const int lane = tid & 31;
  const int wid  = tid >> 5;
  const int e     = g_tile_e[ti];
  const int m0    = g_tile_m0[ti];
  const int valid = g_tile_valid[ti];
  const int n0    = blockIdx.y * 128;

  __shared__ const __half* s_aptr[128];
  extern __shared__ __align__(16) char dsm[];
  const uint32_t dyn0 = smem_u32(dsm);

  if (FIRST && tid < 128) {
    int r   = tid;
    int tok = g_rows_token[m0 + min(r, valid - 1)];
    s_aptr[r] = A + (size_t)tok * Kdim;
  }
  __syncthreads();

  const __half* abase = A + (size_t)m0 * Kdim;          // !FIRST path
  const __half* wbase = W + ((size_t)e * Ndim + n0) * Kdim;
  const int nch = Kdim >> 6;                   // 64 halves per chunk

  const int cr = tid >> 3;                     // base row 0..31
  const int cq = tid & 7;                      // logical 16B quad (0..7)
  const uint32_t dquad = (uint32_t)(((cq + 2*(cr & 3)) & 7) * 16);

  auto issue = [&](int c, uint32_t stoff){
    const uint32_t aS = dyn0 + stoff;
    const uint32_t bS = aS + TILE_BYTES;
    const int k0 = c << 6;                     // halves
    #pragma unroll
    for (int j = 0; j < 4; ++j) {
      const int r = cr + 32 * j;               // (r&3)==(cr&3)
      const __half* srcA = FIRST ? (s_aptr[r] + k0 + cq * 8)
                                 : (abase + (size_t)r * Kdim + k0 + cq * 8);
      CP_ASYNC16(aS + (uint32_t)(r * ROW_BYTES) + dquad, srcA);
      CP_ASYNC16(bS + (uint32_t)(r * ROW_BYTES) + dquad,
                 wbase + (size_t)r * Kdim + k0 + cq * 8);
    }
  };

  issue(0, 0); CP_COMMIT();
  issue(1, STAGE_BYTES); CP_COMMIT();

  const int wRow = wid >> 1;                   // 0..3 -> M*32
  const int wCol = wid & 1;                    // 0..1 -> N*64
  const int g    = lane >> 2;
  const int tig  = lane & 3;

  // per-k16 8B-slot byte offsets (u = 0..3)
  uint32_t off_u[4];
  #pragma unroll
  for (int u = 0; u < 4; ++u)
    off_u[u] = (uint32_t)((((4*u + tig) + 4*(g & 3)) & 15) * 8);

  const uint32_t awb = dyn0 + (uint32_t)((wRow*32 + g) * ROW_BYTES);
  const uint32_t bwb = dyn0 + TILE_BYTES + (uint32_t)((wCol*64 + g) * ROW_BYTES);

  float acc[2][8][4];
  #pragma unroll
  for (int mf = 0; mf < 2; ++mf)
    #pragma unroll
    for (int nf = 0; nf < 8; ++nf)
      #pragma unroll
      for (int q = 0; q < 4; ++q) acc[mf][nf][q] = 0.f;

  uint32_t stoff_c = 0, stoff_n = 2u * STAGE_BYTES;
  for (int c = 0; c < nch; ++c) {
    CP_WAIT(STAGES - 2);
    __syncthreads();
    if (c + STAGES - 1 < nch) issue(c + STAGES - 1, stoff_n);
    CP_COMMIT();

    const uint32_t aw = awb + stoff_c;
    const uint32_t bw = bwb + stoff_c;

    #pragma unroll
    for (int u = 0; u < 4; ++u) {              // four k16 steps per chunk
      const uint32_t au = aw + off_u[u];
      const uint32_t bu = bw + off_u[u];
      uint32_t a0,a1,a2,a3, e0,e1,e2,e3;
      LDS64(a0, a2, au);                       // row wRow*32+g : k-lo, k-hi
      LDS64(a1, a3, au + 8*ROW_BYTES);         // row +8
      LDS64(e0, e2, au + 16*ROW_BYTES);        // mf=1
      LDS64(e1, e3, au + 24*ROW_BYTES);
      #pragma unroll
      for (int nf = 0; nf < 8; ++nf) {
        uint32_t b0, b1;
        LDS64(b0, b1, bu + nf*(8*ROW_BYTES));  // col wCol*64+nf*8+g
        mma_f16(acc[0][nf][0], acc[0][nf][1], acc[0][nf][2], acc[0][nf][3],
                a0, a1, a2, a3, b0, b1);
        mma_f16(acc[1][nf][0], acc[1][nf][1], acc[1][nf][2], acc[1][nf][3],
                e0, e1, e2, e3, b0, b1);
      }
    }
    stoff_c += STAGE_BYTES; if (stoff_c == STAGES*STAGE_BYTES) stoff_c = 0;
    stoff_n += STAGE_BYTES; if (stoff_n == STAGES*STAGE_BYTES) stoff_n = 0;
  }

  // ---------------- epilogue ---------------------------------------------
  const float* bptr = bias + (size_t)e * Ndim + n0;
  #pragma unroll
  for (int mf = 0; mf < 2; ++mf) {
    #pragma unroll
    for (int half = 0; half < 2; ++half) {
      const int rl = wRow * 32 + mf * 16 + g + half * 8;
      if (rl < valid) {
        if (FIRST) {
          // gelu + fp16 round + perm16 scatter:
          // logical cols c0 = wCol*64+nf*8+2tig, c0+1 -> half2 at
          //   (wCol*4 + (nf>>1))*16 + 4*tig + 2*(nf&1)
          __half* orow = (__half*)outv + (size_t)(m0 + rl) * Ndim + n0;
          #pragma unroll
          for (int nf = 0; nf < 8; ++nf) {
            const int nbase = wCol * 64 + nf * 8;
            float v0 = acc[mf][nf][half*2 + 0] + bptr[nbase + 2*tig];
            float v1 = acc[mf][nf][half*2 + 1] + bptr[nbase + 2*tig + 1];
            v0 = gelu_exact(v0); v1 = gelu_exact(v1);
            const int ocol = (wCol*4 + (nf >> 1))*16 + 4*tig + 2*(nf & 1);
            __half2 hv = __floats2half2_rn(v0, v1);
            *(__half2*)(orow + ocol) = hv;
          }
        } else {
          float* orow = (float*)outv + (size_t)(m0 + rl) * Ndim + n0;
          #pragma unroll
          for (int nf = 0; nf < 8; ++nf) {
            const int col = wCol * 64 + nf * 8 + 2*tig;
            float2 v;
            v.x = acc[mf][nf][half*2 + 0] + bptr[col];
            v.y = acc[mf][nf][half*2 + 1] + bptr[col + 1];
            *(float2*)(orow + col) = v;
          }
        }
      }
    }
  }
}

// ------------------------- combine + residual + LN ----------------------
__global__ void __launch_bounds__(256) moe_final_ln(const float* __restrict__ x,
                                                    const float* __restrict__ lnw,
                                                    const float* __restrict__ lnb,
                                                    float* __restrict__ out){
  __shared__ float ps[8], ps2[8], s_mu, s_rs;
  const int t  = blockIdx.x;
  const int r0 = g_token_row[2*t], r1 = g_token_row[2*t+1];
  const float w0 = g_topk_w[2*t],  w1 = g_topk_w[2*t+1];
  const float* xr = x      + (size_t)t  * HDIM;
  const float* a0 = g_out2 + (size_t)r0 * HDIM;
  const float* a1 = g_out2 + (size_t)r1 * HDIM;
  float v[4]; float s = 0.f, s2 = 0.f;
  #pragma unroll
  for (int j = 0; j < 4; ++j) {
    int h = threadIdx.x + 256 * j;
    float val = xr[h] + w0 * a0[h] + w1 * a1[h];
    v[j] = val; s += val; s2 += val * val;
  }
  #pragma unroll
  for (int o = 16; o; o >>= 1) {
    s  += __shfl_xor_sync(0xffffffffu, s,  o);
    s2 += __shfl_xor_sync(0xffffffffu, s2, o);
  }
  const int wd = threadIdx.x >> 5, lane = threadIdx.x & 31;
  if (lane == 0) { ps[wd] = s; ps2[wd] = s2; }
  __syncthreads();
  if (threadIdx.x == 0) {
    float S = 0.f, S2 = 0.f;
    #pragma unroll
    for (int i = 0; i < 8; ++i) { S += ps[i]; S2 += ps2[i]; }
    float mu  = S * (1.f / HDIM);
    float var = S2 * (1.f / HDIM) - mu * mu;
    s_mu = mu; s_rs = rsqrtf(var + 1e-12f);
  }
  __syncthreads();
  const float mu = s_mu, rs = s_rs;
  #pragma unroll
  for (int j = 0; j < 4; ++j) {
    int h = threadIdx.x + 256 * j;
    out[(size_t)t * HDIM + h] = (v[j] - mu) * rs * lnw[h] + lnb[h];
  }
}

// ------------------------- launch ---------------------------------------
extern "C" void kernel_launch(void* const* d_in, const int* in_sizes, int n_in,
                              void* d_out, int out_size){
  (void)in_sizes; (void)n_in; (void)out_size;
  const float* x   = (const float*)d_in[0];
  const float* rw  = (const float*)d_in[1];
  const float* rb  = (const float*)d_in[2];
  const float* w1  = (const float*)d_in[3];
  const float* b1  = (const float*)d_in[4];
  const float* w2  = (const float*)d_in[5];
  const float* b2  = (const float*)d_in[6];
  const float* lnw = (const float*)d_in[7];
  const float* lnb = (const float*)d_in[8];
  float* out = (float*)d_out;

  __half* w1h; cudaGetSymbolAddress((void**)&w1h, g_w1h);
  __half* w2h; cudaGetSymbolAddress((void**)&w2h, g_w2h);
  __half* xhp; cudaGetSymbolAddress((void**)&xhp, g_xh);
  __half* y1p; cudaGetSymbolAddress((void**)&y1p, g_y1h);
  float*  o2p; cudaGetSymbolAddress((void**)&o2p, g_out2);

  cudaFuncSetAttribute(moe_gemm_h<true >, cudaFuncAttributeMaxDynamicSharedMemorySize, DYN_SMEM);
  cudaFuncSetAttribute(moe_gemm_h<false>, cudaFuncAttributeMaxDynamicSharedMemorySize, DYN_SMEM);

  const int N16 = (int)((size_t)NEXP * FFDIM * HDIM / 16);

  round_wh_kernel<<<8192, 256>>>((const float4*)w1, (uint4*)w1h,
                                 (const float4*)w2, (uint4*)w2h, N16);     // 0 (+zero cnt)
  moe_router<<<NTOK/4, 128>>>(x, rw, rb);                                   // 1
  routing_finalize<<<1, 1024>>>();                                         // 2
  moe_gemm_h<true ><<<dim3(144, FFDIM/128), GEMM_THREADS, DYN_SMEM>>>(
      xhp, w1h, b1, y1p, HDIM, FFDIM);                                     // 3: GEMM1 (profiled)
  moe_gemm_h<false><<<dim3(144, HDIM/128), GEMM_THREADS, DYN_SMEM>>>(
      y1p, w2h, b2, o2p, FFDIM, HDIM);                                     // 4: GEMM2
  moe_final_ln<<<NTOK, 256>>>(x, lnw, lnb, out);                           // 5
}